// round 1
// baseline (speedup 1.0000x reference)
#include <cuda_runtime.h>
#include <cuda_fp16.h>
#include <cstdint>
#include <cstdio>

// Problem constants
#define Bc 2048
#define Tc 256
#define Ic 64
#define Hc 128
#define Gc 512               // 4*H
#define Mc (Bc * Tc)         // 524288 tokens

// ---------------------------------------------------------------------------
// Scratch (device globals; no allocation allowed)
// ---------------------------------------------------------------------------
__device__ float g_pre[(size_t)Tc * Bc * Gc];   // [T][B][4H]   (reused by both layers)
__device__ float g_seq0[(size_t)Bc * Tc * Hc];  // layer0 hidden sequence [B][T][H]
__device__ float g_seq1[(size_t)Bc * Tc * Hc];  // layer1 hidden sequence [B][T][H]
__device__ float g_scores[(size_t)Bc * Tc];     // attention logits [B][T]

// ---------------------------------------------------------------------------
// Fast activations (fp32, MUFU-based; accurate to ~1e-6 rel)
// ---------------------------------------------------------------------------
__device__ __forceinline__ float fsig(float x) {
    return __fdividef(1.0f, 1.0f + __expf(-x));
}
__device__ __forceinline__ float ftanh_(float x) {
    float ax = fabsf(x);
    float t  = __expf(-2.0f * ax);
    float r  = __fdividef(1.0f - t, 1.0f + t);
    return copysignf(r, x);
}

// ---------------------------------------------------------------------------
// Pre-GEMM:  out[t][b][n] = sum_k A[(b*T+t)*K + k] * W[n*K + k] + b1[n] + b2[n]
// Block: 64 rows (m) x 256 cols (n).  256 threads, each 16r x 4n micro-tile.
// W tile stored k-major in SMEM (transposed) for conflict-free float4 loads.
// ---------------------------------------------------------------------------
template <int K>
__global__ __launch_bounds__(256)
void gemm_pre_kernel(const float* __restrict__ A,
                     const float* __restrict__ W,
                     const float* __restrict__ b1,
                     const float* __restrict__ b2,
                     float* __restrict__ out)
{
    constexpr int NT  = 256;
    constexpr int MT  = 64;
    constexpr int NTP = NT + 4;                    // pad keeps float4 alignment + kills conflicts
    extern __shared__ float sm[];
    float* wT  = sm;                               // [K][NTP]
    float* Asm = sm + K * NTP;                     // [MT][K]

    const int tid = threadIdx.x;
    const int m0  = blockIdx.x * MT;
    const int n0  = blockIdx.y * NT;

    // Stage W (transposed) and A
    for (int idx = tid; idx < NT * K; idx += 256) {
        int n = idx / K, k = idx % K;
        wT[k * NTP + n] = W[(size_t)(n0 + n) * K + k];
    }
    {
        const float4* Ag  = reinterpret_cast<const float4*>(A + (size_t)m0 * K);
        float4*       As4 = reinterpret_cast<float4*>(Asm);
        for (int idx = tid; idx < MT * K / 4; idx += 256) As4[idx] = Ag[idx];
    }
    __syncthreads();

    const int gg = tid & 63;      // n-group (4 consecutive n)
    const int rg = tid >> 6;      // r-group (16 rows)

    float acc[16][4];
#pragma unroll
    for (int i = 0; i < 16; i++) { acc[i][0] = acc[i][1] = acc[i][2] = acc[i][3] = 0.f; }

#pragma unroll 2
    for (int k4 = 0; k4 < K; k4 += 4) {
        float4 wv0 = *reinterpret_cast<const float4*>(&wT[(k4 + 0) * NTP + 4 * gg]);
        float4 wv1 = *reinterpret_cast<const float4*>(&wT[(k4 + 1) * NTP + 4 * gg]);
        float4 wv2 = *reinterpret_cast<const float4*>(&wT[(k4 + 2) * NTP + 4 * gg]);
        float4 wv3 = *reinterpret_cast<const float4*>(&wT[(k4 + 3) * NTP + 4 * gg]);
#pragma unroll
        for (int rr = 0; rr < 16; rr++) {
            float4 av = *reinterpret_cast<const float4*>(&Asm[(rg * 16 + rr) * K + k4]);
            acc[rr][0] = fmaf(av.x, wv0.x, fmaf(av.y, wv1.x, fmaf(av.z, wv2.x, fmaf(av.w, wv3.x, acc[rr][0]))));
            acc[rr][1] = fmaf(av.x, wv0.y, fmaf(av.y, wv1.y, fmaf(av.z, wv2.y, fmaf(av.w, wv3.y, acc[rr][1]))));
            acc[rr][2] = fmaf(av.x, wv0.z, fmaf(av.y, wv1.z, fmaf(av.z, wv2.z, fmaf(av.w, wv3.z, acc[rr][2]))));
            acc[rr][3] = fmaf(av.x, wv0.w, fmaf(av.y, wv1.w, fmaf(av.z, wv2.w, fmaf(av.w, wv3.w, acc[rr][3]))));
        }
    }

    const int n = n0 + 4 * gg;
    float4 b1v = *reinterpret_cast<const float4*>(b1 + n);
    float4 b2v = *reinterpret_cast<const float4*>(b2 + n);
    float bx = b1v.x + b2v.x, by = b1v.y + b2v.y, bz = b1v.z + b2v.z, bw = b1v.w + b2v.w;

#pragma unroll
    for (int rr = 0; rr < 16; rr++) {
        int m = m0 + rg * 16 + rr;
        int bidx = m >> 8;          // m / T
        int t    = m & 255;         // m % T
        float4 res = make_float4(acc[rr][0] + bx, acc[rr][1] + by, acc[rr][2] + bz, acc[rr][3] + bw);
        *reinterpret_cast<float4*>(&out[((size_t)t * Bc + bidx) * Gc + n]) = res;
    }
}

// ---------------------------------------------------------------------------
// LSTM recurrence: block owns 16 batch rows for the whole sequence.
// w_hh in SMEM as fp16 (k-major transposed), h in SMEM, c in registers.
// gates[r][g] = pre[t][b0+r][g] + sum_k h[r][k]*w_hh[g][k]
// ---------------------------------------------------------------------------
__global__ __launch_bounds__(256)
void lstm_rec_kernel(const float* __restrict__ pre,
                     const float* __restrict__ w_hh,
                     float* __restrict__ out)   // [B][T][H]
{
    extern __shared__ char smraw[];
    __half* wT    = reinterpret_cast<__half*>(smraw);                 // [128][512] k-major
    float*  h_sm  = reinterpret_cast<float*>(smraw + 128 * 512 * 2);  // [16][128]
    float*  gates = h_sm + 16 * 128;                                  // [16][512]

    const int tid = threadIdx.x;
    const int b0  = blockIdx.x * 16;

    for (int idx = tid; idx < Gc * Hc; idx += 256) {
        int g = idx >> 7, k = idx & 127;
        wT[k * Gc + g] = __float2half_rn(w_hh[idx]);
    }
    for (int idx = tid; idx < 16 * Hc; idx += 256) h_sm[idx] = 0.f;

    float c[8];
#pragma unroll
    for (int j = 0; j < 8; j++) c[j] = 0.f;
    __syncthreads();

    const int gg = tid & 127;   // gate group: 4 consecutive gates
    const int rg = tid >> 7;    // row group: 8 rows

    for (int t = 0; t < Tc; t++) {
        float acc[8][4];
        const float* prow = pre + ((size_t)t * Bc + b0) * Gc + 4 * gg;
#pragma unroll
        for (int rr = 0; rr < 8; rr++) {
            float4 p = *reinterpret_cast<const float4*>(prow + (size_t)(rg * 8 + rr) * Gc);
            acc[rr][0] = p.x; acc[rr][1] = p.y; acc[rr][2] = p.z; acc[rr][3] = p.w;
        }

#pragma unroll 2
        for (int k4 = 0; k4 < Hc; k4 += 4) {
            float4 wf[4];
#pragma unroll
            for (int j = 0; j < 4; j++) {
                uint2 u = *reinterpret_cast<const uint2*>(&wT[(k4 + j) * Gc + 4 * gg]);
                __half2 ha = *reinterpret_cast<__half2*>(&u.x);
                __half2 hb = *reinterpret_cast<__half2*>(&u.y);
                float2 fa = __half22float2(ha);
                float2 fb = __half22float2(hb);
                wf[j] = make_float4(fa.x, fa.y, fb.x, fb.y);
            }
#pragma unroll
            for (int rr = 0; rr < 8; rr++) {
                float4 hv = *reinterpret_cast<const float4*>(&h_sm[(rg * 8 + rr) * Hc + k4]);
                acc[rr][0] = fmaf(hv.x, wf[0].x, fmaf(hv.y, wf[1].x, fmaf(hv.z, wf[2].x, fmaf(hv.w, wf[3].x, acc[rr][0]))));
                acc[rr][1] = fmaf(hv.x, wf[0].y, fmaf(hv.y, wf[1].y, fmaf(hv.z, wf[2].y, fmaf(hv.w, wf[3].y, acc[rr][1]))));
                acc[rr][2] = fmaf(hv.x, wf[0].z, fmaf(hv.y, wf[1].z, fmaf(hv.z, wf[2].z, fmaf(hv.w, wf[3].z, acc[rr][2]))));
                acc[rr][3] = fmaf(hv.x, wf[0].w, fmaf(hv.y, wf[1].w, fmaf(hv.z, wf[2].w, fmaf(hv.w, wf[3].w, acc[rr][3]))));
            }
        }

#pragma unroll
        for (int rr = 0; rr < 8; rr++) {
            *reinterpret_cast<float4*>(&gates[(rg * 8 + rr) * Gc + 4 * gg]) =
                make_float4(acc[rr][0], acc[rr][1], acc[rr][2], acc[rr][3]);
        }
        __syncthreads();

#pragma unroll
        for (int j = 0; j < 8; j++) {
            int e  = tid + j * 256;
            int r  = e >> 7;
            int hc = e & 127;
            float gi = gates[r * Gc + hc];
            float gf = gates[r * Gc + 128 + hc];
            float gz = gates[r * Gc + 256 + hc];
            float go = gates[r * Gc + 384 + hc];
            float i_ = fsig(gi);
            float f_ = fsig(gf);
            float z_ = ftanh_(gz);
            float o_ = fsig(go);
            float cn = fmaf(f_, c[j], i_ * z_);
            c[j] = cn;
            float hv = o_ * ftanh_(cn);
            h_sm[r * Hc + hc] = hv;
            out[((size_t)(b0 + r) * Tc + t) * Hc + hc] = hv;
        }
        __syncthreads();
    }
}

// ---------------------------------------------------------------------------
// Attention scores: s[m] = tanh(seq[m]@aw1^T + ab1) . aw2 + ab2
// Block: 64 tokens. 256 threads, 8 warps: warp = 8 rows x full 128 cols.
// ---------------------------------------------------------------------------
__global__ __launch_bounds__(256)
void attn_score_kernel(const float* __restrict__ seq,
                       const float* __restrict__ aw1,
                       const float* __restrict__ ab1,
                       const float* __restrict__ aw2,
                       const float* __restrict__ ab2,
                       float* __restrict__ scores)
{
    constexpr int MT = 64;
    constexpr int NP = 132;      // 128 + pad
    extern __shared__ float sm[];
    float* wT  = sm;             // [128][NP]  (k-major aw1)
    float* Asm = sm + 128 * NP;  // [64][128]

    const int tid = threadIdx.x;
    const int m0  = blockIdx.x * MT;

    for (int idx = tid; idx < 128 * 128; idx += 256) {
        int n = idx >> 7, k = idx & 127;
        wT[k * NP + n] = aw1[idx];
    }
    {
        const float4* Ag  = reinterpret_cast<const float4*>(seq + (size_t)m0 * Hc);
        float4*       As4 = reinterpret_cast<float4*>(Asm);
        for (int idx = tid; idx < MT * Hc / 4; idx += 256) As4[idx] = Ag[idx];
    }
    __syncthreads();

    const int gg = tid & 31;   // 32 col-groups of 4
    const int rg = tid >> 5;   // 8 row-groups of 8 (= warp id)

    float acc[8][4];
#pragma unroll
    for (int i = 0; i < 8; i++) { acc[i][0] = acc[i][1] = acc[i][2] = acc[i][3] = 0.f; }

#pragma unroll 2
    for (int k4 = 0; k4 < 128; k4 += 4) {
        float4 wv0 = *reinterpret_cast<const float4*>(&wT[(k4 + 0) * NP + 4 * gg]);
        float4 wv1 = *reinterpret_cast<const float4*>(&wT[(k4 + 1) * NP + 4 * gg]);
        float4 wv2 = *reinterpret_cast<const float4*>(&wT[(k4 + 2) * NP + 4 * gg]);
        float4 wv3 = *reinterpret_cast<const float4*>(&wT[(k4 + 3) * NP + 4 * gg]);
#pragma unroll
        for (int rr = 0; rr < 8; rr++) {
            float4 av = *reinterpret_cast<const float4*>(&Asm[(rg * 8 + rr) * 128 + k4]);
            acc[rr][0] = fmaf(av.x, wv0.x, fmaf(av.y, wv1.x, fmaf(av.z, wv2.x, fmaf(av.w, wv3.x, acc[rr][0]))));
            acc[rr][1] = fmaf(av.x, wv0.y, fmaf(av.y, wv1.y, fmaf(av.z, wv2.y, fmaf(av.w, wv3.y, acc[rr][1]))));
            acc[rr][2] = fmaf(av.x, wv0.z, fmaf(av.y, wv1.z, fmaf(av.z, wv2.z, fmaf(av.w, wv3.z, acc[rr][2]))));
            acc[rr][3] = fmaf(av.x, wv0.w, fmaf(av.y, wv1.w, fmaf(av.z, wv2.w, fmaf(av.w, wv3.w, acc[rr][3]))));
        }
    }

    float4 b1v = *reinterpret_cast<const float4*>(ab1 + 4 * gg);
    float4 w2v = *reinterpret_cast<const float4*>(aw2 + 4 * gg);
    float  bs  = ab2[0];

#pragma unroll
    for (int rr = 0; rr < 8; rr++) {
        float p = ftanh_(acc[rr][0] + b1v.x) * w2v.x
                + ftanh_(acc[rr][1] + b1v.y) * w2v.y
                + ftanh_(acc[rr][2] + b1v.z) * w2v.z
                + ftanh_(acc[rr][3] + b1v.w) * w2v.w;
#pragma unroll
        for (int off = 16; off > 0; off >>= 1) p += __shfl_xor_sync(0xffffffffu, p, off);
        if (gg == 0) scores[m0 + rg * 8 + rr] = p + bs;
    }
}

// ---------------------------------------------------------------------------
// Softmax over T + context + MLP head.  One block per batch row, 128 threads.
// ---------------------------------------------------------------------------
__global__ __launch_bounds__(128)
void head_kernel(const float* __restrict__ seq,
                 const float* __restrict__ scores,
                 const float* __restrict__ fw1, const float* __restrict__ fb1,
                 const float* __restrict__ fw2, const float* __restrict__ fb2,
                 const float* __restrict__ fw3, const float* __restrict__ fb3,
                 float* __restrict__ out)
{
    extern __shared__ float sm[];
    float* wbuf = sm;                    // [128*129]
    float* attn = wbuf + 128 * 129;      // [256]
    float* ctx  = attn + 256;            // [128]
    float* h1   = ctx + 128;             // [128]
    float* h2   = h1 + 128;              // [64]
    float* red  = h2 + 64;               // [4]

    const int b   = blockIdx.x;
    const int tid = threadIdx.x;
    const int wid = tid >> 5;
    const int lid = tid & 31;

    // ---- softmax over T=256 (2 scores per thread) ----
    float s0 = scores[(size_t)b * Tc + tid];
    float s1 = scores[(size_t)b * Tc + 128 + tid];
    float mx = fmaxf(s0, s1);
#pragma unroll
    for (int off = 16; off > 0; off >>= 1) mx = fmaxf(mx, __shfl_xor_sync(0xffffffffu, mx, off));
    if (lid == 0) red[wid] = mx;
    __syncthreads();
    float m4 = fmaxf(fmaxf(red[0], red[1]), fmaxf(red[2], red[3]));
    __syncthreads();

    float e0 = __expf(s0 - m4);
    float e1 = __expf(s1 - m4);
    float ps = e0 + e1;
#pragma unroll
    for (int off = 16; off > 0; off >>= 1) ps += __shfl_xor_sync(0xffffffffu, ps, off);
    if (lid == 0) red[wid] = ps;
    __syncthreads();
    float total = red[0] + red[1] + red[2] + red[3];
    float inv = __fdividef(1.0f, total);
    attn[tid]       = e0 * inv;
    attn[tid + 128] = e1 * inv;
    __syncthreads();

    // ---- context: ctx[hc] = sum_t attn[t] * seq[b][t][hc] ----
    {
        const float* sp = seq + (size_t)b * Tc * Hc + tid;
        float acc = 0.f;
#pragma unroll 4
        for (int t = 0; t < Tc; t++) acc = fmaf(attn[t], sp[(size_t)t * Hc], acc);
        ctx[tid] = acc;
    }

    // ---- fc1: h1 = relu(fw1 @ ctx + fb1) ----
    for (int idx = tid; idx < 128 * 128; idx += 128) {
        int j = idx >> 7, k = idx & 127;
        wbuf[j * 129 + k] = fw1[idx];
    }
    __syncthreads();
    {
        float a1 = fb1[tid];
        const float* wr = wbuf + tid * 129;
#pragma unroll 4
        for (int k = 0; k < 128; k++) a1 = fmaf(wr[k], ctx[k], a1);
        h1[tid] = fmaxf(a1, 0.f);
    }
    __syncthreads();

    // ---- fc2: h2 = relu(fw2 @ h1 + fb2) ----
    for (int idx = tid; idx < 64 * 128; idx += 128) {
        int j = idx >> 7, k = idx & 127;
        wbuf[j * 129 + k] = fw2[idx];
    }
    __syncthreads();
    if (tid < 64) {
        float a2 = fb2[tid];
        const float* wr = wbuf + tid * 129;
#pragma unroll 4
        for (int k = 0; k < 128; k++) a2 = fmaf(wr[k], h1[k], a2);
        h2[tid] = fmaxf(a2, 0.f);
    }
    __syncthreads();

    // ---- fc3: scalar output ----
    float p = (tid < 64) ? fw3[tid] * h2[tid] : 0.f;
#pragma unroll
    for (int off = 16; off > 0; off >>= 1) p += __shfl_xor_sync(0xffffffffu, p, off);
    if (lid == 0) red[wid] = p;
    __syncthreads();
    if (tid == 0) out[b] = red[0] + red[1] + red[2] + red[3] + fb3[0];
}

// ---------------------------------------------------------------------------
// Launch
// ---------------------------------------------------------------------------
extern "C" void kernel_launch(void* const* d_in, const int* in_sizes, int n_in,
                              void* d_out, int out_size)
{
    const float* x     = (const float*)d_in[0];
    const float* w_ih0 = (const float*)d_in[1];
    const float* w_hh0 = (const float*)d_in[2];
    const float* b_ih0 = (const float*)d_in[3];
    const float* b_hh0 = (const float*)d_in[4];
    const float* w_ih1 = (const float*)d_in[5];
    const float* w_hh1 = (const float*)d_in[6];
    const float* b_ih1 = (const float*)d_in[7];
    const float* b_hh1 = (const float*)d_in[8];
    const float* aw1   = (const float*)d_in[9];
    const float* ab1   = (const float*)d_in[10];
    const float* aw2   = (const float*)d_in[11];
    const float* ab2   = (const float*)d_in[12];
    const float* fw1   = (const float*)d_in[13];
    const float* fb1   = (const float*)d_in[14];
    const float* fw2   = (const float*)d_in[15];
    const float* fb2   = (const float*)d_in[16];
    const float* fw3   = (const float*)d_in[17];
    const float* fb3   = (const float*)d_in[18];
    float* out = (float*)d_out;

    float *pre_p, *seq0_p, *seq1_p, *scores_p;
    cudaGetSymbolAddress((void**)&pre_p,    g_pre);
    cudaGetSymbolAddress((void**)&seq0_p,   g_seq0);
    cudaGetSymbolAddress((void**)&seq1_p,   g_seq1);
    cudaGetSymbolAddress((void**)&scores_p, g_scores);

    // SMEM sizes
    const int sm_g64  = (64  * 260 + 64 * 64)  * 4;   // 82944
    const int sm_g128 = (128 * 260 + 64 * 128) * 4;   // 165888
    const int sm_rec  = 128 * 512 * 2 + (16 * 128 + 16 * 512) * 4;  // 172032
    const int sm_attn = (128 * 132 + 64 * 128) * 4;   // 100352
    const int sm_head = (128 * 129 + 256 + 128 + 128 + 64 + 4) * 4; // ~68.5KB

    cudaFuncSetAttribute(gemm_pre_kernel<64>,  cudaFuncAttributeMaxDynamicSharedMemorySize, sm_g64);
    cudaFuncSetAttribute(gemm_pre_kernel<128>, cudaFuncAttributeMaxDynamicSharedMemorySize, sm_g128);
    cudaFuncSetAttribute(lstm_rec_kernel,      cudaFuncAttributeMaxDynamicSharedMemorySize, sm_rec);
    cudaFuncSetAttribute(attn_score_kernel,    cudaFuncAttributeMaxDynamicSharedMemorySize, sm_attn);
    cudaFuncSetAttribute(head_kernel,          cudaFuncAttributeMaxDynamicSharedMemorySize, sm_head);

    dim3 ggrid(Mc / 64, 2);

    // Layer 0
    gemm_pre_kernel<64><<<ggrid, 256, sm_g64>>>(x, w_ih0, b_ih0, b_hh0, pre_p);
    lstm_rec_kernel<<<Bc / 16, 256, sm_rec>>>(pre_p, w_hh0, seq0_p);

    // Layer 1
    gemm_pre_kernel<128><<<ggrid, 256, sm_g128>>>(seq0_p, w_ih1, b_ih1, b_hh1, pre_p);
    lstm_rec_kernel<<<Bc / 16, 256, sm_rec>>>(pre_p, w_hh1, seq1_p);

    // Attention scores
    attn_score_kernel<<<Mc / 64, 256, sm_attn>>>(seq1_p, aw1, ab1, aw2, ab2, scores_p);

    // Softmax + context + MLP head
    head_kernel<<<Bc, 128, sm_head>>>(seq1_p, scores_p, fw1, fb1, fw2, fb2, fw3, fb3, out);
}

// round 2
// speedup vs baseline: 3.6713x; 3.6713x over previous
#include <cuda_runtime.h>
#include <cuda_fp16.h>
#include <cstdint>

#define Bc 2048
#define Tc 256
#define Ic 64
#define Hc 128
#define Gc 512
#define Mc (Bc * Tc)

// ---------------------------------------------------------------------------
// Scratch (device globals; no allocation allowed)
// ---------------------------------------------------------------------------
__device__ __half g_pre[(size_t)Tc * Bc * Gc];   // [T][B][4H] fp16 (reused per layer)
__device__ __half g_seq0[(size_t)Mc * Hc];       // layer0 hidden [B][T][H] fp16
__device__ __half g_seq1[(size_t)Mc * Hc];       // layer1 hidden [B][T][H] fp16
__device__ float  g_scores[(size_t)Bc * Tc];     // attention logits [B][T]

// ---------------------------------------------------------------------------
// PTX helpers
// ---------------------------------------------------------------------------
__device__ __forceinline__ uint32_t su32(const void* p) {
    return (uint32_t)__cvta_generic_to_shared(p);
}
__device__ __forceinline__ void ldsm4(uint32_t a, uint32_t& r0, uint32_t& r1,
                                      uint32_t& r2, uint32_t& r3) {
    asm volatile("ldmatrix.sync.aligned.m8n8.x4.shared.b16 {%0,%1,%2,%3},[%4];"
                 : "=r"(r0), "=r"(r1), "=r"(r2), "=r"(r3) : "r"(a));
}
__device__ __forceinline__ void mma16816(float* d, const uint32_t* a, const uint32_t* b) {
    asm volatile(
        "mma.sync.aligned.m16n8k16.row.col.f32.f16.f16.f32 "
        "{%0,%1,%2,%3},{%4,%5,%6,%7},{%8,%9},{%0,%1,%2,%3};"
        : "+f"(d[0]), "+f"(d[1]), "+f"(d[2]), "+f"(d[3])
        : "r"(a[0]), "r"(a[1]), "r"(a[2]), "r"(a[3]), "r"(b[0]), "r"(b[1]));
}
__device__ __forceinline__ float tanh_f(float x) {
    float y; asm("tanh.approx.f32 %0,%1;" : "=f"(y) : "f"(x)); return y;
}
__device__ __forceinline__ float sig_f(float x) {
    return fmaf(tanh_f(0.5f * x), 0.5f, 0.5f);
}
__device__ __forceinline__ void cpa16(uint32_t d, const void* s) {
    asm volatile("cp.async.cg.shared.global [%0],[%1],16;" :: "r"(d), "l"(s));
}

// ---------------------------------------------------------------------------
// Pre-GEMM (HMMA): out[t][b][n] = A[m]·W[n] + b1[n] + b2[n], fp16 out
// Block tile 128m x 128n, full K. 8 warps (4m x 2n), warp tile 32m x 64n.
// ---------------------------------------------------------------------------
template <int K, bool AHALF>
__global__ __launch_bounds__(256)
void gemm_pre_hmma(const void* __restrict__ Araw,
                   const float* __restrict__ W,
                   const float* __restrict__ b1f,
                   const float* __restrict__ b2f,
                   __half* __restrict__ out)
{
    constexpr int KP = K + 8;
    extern __shared__ char smraw[];
    __half* As = (__half*)smraw;            // [128][KP]
    __half* Bs = As + 128 * KP;             // [128][KP]  (W rows n0..n0+127)
    float*  bsum = (float*)(Bs + 128 * KP); // [128]

    const int tid = threadIdx.x;
    const int m0 = blockIdx.x * 128, n0 = blockIdx.y * 128;

    if (AHALF) {
        const uint4* Ag = (const uint4*)((const __half*)Araw + (size_t)m0 * K);
        for (int i = tid; i < 128 * K / 8; i += 256) {
            int r = i / (K / 8), ch = i % (K / 8);
            *(uint4*)(As + r * KP + ch * 8) = Ag[i];
        }
    } else {
        const float4* Ag = (const float4*)((const float*)Araw + (size_t)m0 * K);
        for (int i = tid; i < 128 * K / 4; i += 256) {
            int r = i / (K / 4), ch = i % (K / 4);
            float4 v = Ag[i];
            *(__half2*)(As + r * KP + ch * 4)     = __floats2half2_rn(v.x, v.y);
            *(__half2*)(As + r * KP + ch * 4 + 2) = __floats2half2_rn(v.z, v.w);
        }
    }
    {
        const float4* Wg = (const float4*)(W + (size_t)n0 * K);
        for (int i = tid; i < 128 * K / 4; i += 256) {
            int r = i / (K / 4), ch = i % (K / 4);
            float4 v = Wg[i];
            *(__half2*)(Bs + r * KP + ch * 4)     = __floats2half2_rn(v.x, v.y);
            *(__half2*)(Bs + r * KP + ch * 4 + 2) = __floats2half2_rn(v.z, v.w);
        }
    }
    if (tid < 128) bsum[tid] = b1f[n0 + tid] + b2f[n0 + tid];
    __syncthreads();

    const int wid = tid >> 5, lane = tid & 31;
    const int wm = wid & 3, wn = wid >> 2;
    const int mat = lane >> 3, lr = lane & 7;

    float acc[2][8][4];
#pragma unroll
    for (int i = 0; i < 2; i++)
#pragma unroll
        for (int j = 0; j < 8; j++)
#pragma unroll
            for (int l = 0; l < 4; l++) acc[i][j][l] = 0.f;

#pragma unroll
    for (int kt = 0; kt < K / 16; kt++) {
        uint32_t a[2][4];
#pragma unroll
        for (int mt = 0; mt < 2; mt++) {
            int row = wm * 32 + mt * 16 + (mat & 1) * 8 + lr;
            int col = kt * 16 + (mat >> 1) * 8;
            ldsm4(su32(As + row * KP + col), a[mt][0], a[mt][1], a[mt][2], a[mt][3]);
        }
        uint32_t b[8][2];
#pragma unroll
        for (int nq = 0; nq < 4; nq++) {
            int nrow = wn * 64 + nq * 16 + (mat >> 1) * 8 + lr;
            int col  = kt * 16 + (mat & 1) * 8;
            uint32_t r0, r1, r2, r3;
            ldsm4(su32(Bs + nrow * KP + col), r0, r1, r2, r3);
            b[nq * 2][0] = r0; b[nq * 2][1] = r1;
            b[nq * 2 + 1][0] = r2; b[nq * 2 + 1][1] = r3;
        }
#pragma unroll
        for (int mt = 0; mt < 2; mt++)
#pragma unroll
            for (int nt = 0; nt < 8; nt++)
                mma16816(acc[mt][nt], a[mt], b[nt]);
    }

    // epilogue: add bias, store fp16 at [t][b][n]
#pragma unroll
    for (int mt = 0; mt < 2; mt++) {
#pragma unroll
        for (int nt = 0; nt < 8; nt++) {
            int lc = wn * 64 + nt * 8 + 2 * (lane & 3);
            float2 bs = *(float2*)&bsum[lc];
            int c = n0 + lc;
#pragma unroll
            for (int hh = 0; hh < 2; hh++) {
                int r = m0 + wm * 32 + mt * 16 + (lane >> 2) + hh * 8;
                int bi = r >> 8, tt = r & 255;
                size_t off = ((size_t)tt * Bc + bi) * Gc + c;
                *(__half2*)&out[off] =
                    __floats2half2_rn(acc[mt][nt][hh * 2] + bs.x,
                                      acc[mt][nt][hh * 2 + 1] + bs.y);
            }
        }
    }
}

// ---------------------------------------------------------------------------
// LSTM recurrence (HMMA): block = 16 batch rows, 8 warps.
// w_hh held entirely in registers as fp16 B-fragments (persistent, 128 regs).
// pre staged by cp.async double-buffer; gates fully register-local per warp.
// ---------------------------------------------------------------------------
__global__ __launch_bounds__(256)
void lstm_rec_hmma(const __half* __restrict__ pre,    // [T][B][512]
                   const float*  __restrict__ w_hh,   // [512][128]
                   __half* __restrict__ seqout)       // [B][T][128]
{
    __shared__ __half h_sm[2][16][136];
    __shared__ __half pre_sm[2][16][520];

    const int tid = threadIdx.x, wid = tid >> 5, lane = tid & 31;
    const int b0 = blockIdx.x * 16;

    // Persistent B fragments: warp wid owns gate-cols {128g + 16*wid + 8p}
    uint32_t bf[8][8][2];
    {
        const int n_off = lane >> 2;
        const int k_off = 2 * (lane & 3);
#pragma unroll
        for (int nt = 0; nt < 8; nt++) {
            int n = 128 * (nt >> 1) + 16 * wid + 8 * (nt & 1) + n_off;
            const float* wr = w_hh + (size_t)n * Hc + k_off;
#pragma unroll
            for (int kt = 0; kt < 8; kt++) {
                float2 v0 = *(const float2*)(wr + kt * 16);
                float2 v1 = *(const float2*)(wr + kt * 16 + 8);
                __half2 h0 = __floats2half2_rn(v0.x, v0.y);
                __half2 h1 = __floats2half2_rn(v1.x, v1.y);
                bf[kt][nt][0] = *(uint32_t*)&h0;
                bf[kt][nt][1] = *(uint32_t*)&h1;
            }
        }
    }

    for (int i = tid; i < 2 * 16 * 136; i += 256)
        ((__half*)h_sm)[i] = __float2half(0.f);

    // prefetch pre(t=0)
#pragma unroll
    for (int j = 0; j < 4; j++) {
        int idx = tid + j * 256;
        int r = idx >> 6, ch = idx & 63;
        cpa16(su32(&pre_sm[0][r][ch * 8]),
              pre + ((size_t)b0 + r) * Gc + ch * 8);
    }
    asm volatile("cp.async.commit_group;");

    float cst[8];
#pragma unroll
    for (int j = 0; j < 8; j++) cst[j] = 0.f;

    asm volatile("cp.async.wait_group 0;");
    __syncthreads();

    const int mat = lane >> 3, lr = lane & 7;
    const int r_lo = lane >> 2;
    const int c_loc = 2 * (lane & 3);

    for (int t = 0; t < Tc; t++) {
        const int cur = t & 1, nxt = cur ^ 1;

        // acc init from pre tile (C-fragment layout == non-trans ldmatrix frag)
        float acc[8][4];
#pragma unroll
        for (int g = 0; g < 4; g++) {
            int row = (mat & 1) * 8 + lr;
            int col = 128 * g + 16 * wid + (mat >> 1) * 8;
            uint32_t r0, r1, r2, r3;
            ldsm4(su32(&pre_sm[cur][row][col]), r0, r1, r2, r3);
            float2 f0 = __half22float2(*(__half2*)&r0);
            float2 f1 = __half22float2(*(__half2*)&r1);
            float2 f2 = __half22float2(*(__half2*)&r2);
            float2 f3 = __half22float2(*(__half2*)&r3);
            acc[g * 2][0] = f0.x; acc[g * 2][1] = f0.y;
            acc[g * 2][2] = f1.x; acc[g * 2][3] = f1.y;
            acc[g * 2 + 1][0] = f2.x; acc[g * 2 + 1][1] = f2.y;
            acc[g * 2 + 1][2] = f3.x; acc[g * 2 + 1][3] = f3.y;
        }

        // prefetch pre(t+1) (hidden behind MMA)
        if (t + 1 < Tc) {
#pragma unroll
            for (int j = 0; j < 4; j++) {
                int idx = tid + j * 256;
                int r = idx >> 6, ch = idx & 63;
                cpa16(su32(&pre_sm[nxt][r][ch * 8]),
                      pre + ((size_t)(t + 1) * Bc + b0 + r) * Gc + ch * 8);
            }
        }
        asm volatile("cp.async.commit_group;");

        // gates += h(t-1) @ w_hh^T
#pragma unroll
        for (int kt = 0; kt < 8; kt++) {
            uint32_t a[4];
            a[0] = *(const uint32_t*)&h_sm[cur][r_lo    ][kt * 16 + c_loc];
            a[1] = *(const uint32_t*)&h_sm[cur][r_lo + 8][kt * 16 + c_loc];
            a[2] = *(const uint32_t*)&h_sm[cur][r_lo    ][kt * 16 + c_loc + 8];
            a[3] = *(const uint32_t*)&h_sm[cur][r_lo + 8][kt * 16 + c_loc + 8];
#pragma unroll
            for (int nt = 0; nt < 8; nt++) mma16816(acc[nt], a, bf[kt][nt]);
        }

        // register-local LSTM cell
#pragma unroll
        for (int p = 0; p < 2; p++) {
#pragma unroll
            for (int jr = 0; jr < 2; jr++) {
                float hv0 = 0.f, hv1 = 0.f;
#pragma unroll
                for (int jc = 0; jc < 2; jc++) {
                    int j = jr * 2 + jc;
                    float i_ = sig_f(acc[0 + p][j]);
                    float f_ = sig_f(acc[2 + p][j]);
                    float z_ = tanh_f(acc[4 + p][j]);
                    float o_ = sig_f(acc[6 + p][j]);
                    float cn = fmaf(f_, cst[p * 4 + j], i_ * z_);
                    cst[p * 4 + j] = cn;
                    float hv = o_ * tanh_f(cn);
                    if (jc == 0) hv0 = hv; else hv1 = hv;
                }
                __half2 hh = __floats2half2_rn(hv0, hv1);
                int rr = r_lo + jr * 8;
                int cc = 16 * wid + 8 * p + c_loc;
                *(__half2*)&h_sm[nxt][rr][cc] = hh;
                *(__half2*)&seqout[((size_t)(b0 + rr) * Tc + t) * Hc + cc] = hh;
            }
        }
        asm volatile("cp.async.wait_group 0;");
        __syncthreads();
    }
}

// ---------------------------------------------------------------------------
// Attention scores (HMMA): s[m] = tanh(seq[m]@aw1^T + ab1)·aw2 + ab2
// Block = 128 rows; warp = 16 rows x all 128 cols; row-sum via quad shfl.
// ---------------------------------------------------------------------------
__global__ __launch_bounds__(256)
void attn_score_hmma(const __half* __restrict__ seq,
                     const float* __restrict__ aw1,
                     const float* __restrict__ ab1,
                     const float* __restrict__ aw2,
                     const float* __restrict__ ab2,
                     float* __restrict__ scores)
{
    extern __shared__ char smraw[];
    __half* As = (__half*)smraw;             // [128][136]
    __half* Bs = As + 128 * 136;             // [128][136] aw1 as [n][k]
    float*  abw = (float*)(Bs + 128 * 136);  // [256] = ab1 | aw2

    const int tid = threadIdx.x, wid = tid >> 5, lane = tid & 31;
    const int m0 = blockIdx.x * 128;

    {
        const uint4* Ag = (const uint4*)(seq + (size_t)m0 * Hc);
        for (int i = tid; i < 128 * 16; i += 256) {
            int r = i >> 4, ch = i & 15;
            *(uint4*)(As + r * 136 + ch * 8) = Ag[i];
        }
        const float4* Wg = (const float4*)aw1;
        for (int i = tid; i < 128 * 32; i += 256) {
            int r = i >> 5, ch = i & 31;
            float4 v = Wg[i];
            *(__half2*)(Bs + r * 136 + ch * 4)     = __floats2half2_rn(v.x, v.y);
            *(__half2*)(Bs + r * 136 + ch * 4 + 2) = __floats2half2_rn(v.z, v.w);
        }
        if (tid < 128) abw[tid] = ab1[tid];
        else if (tid < 256) abw[tid] = aw2[tid - 128];
    }
    __syncthreads();

    const int mat = lane >> 3, lr = lane & 7;
    float acc[16][4];
#pragma unroll
    for (int i = 0; i < 16; i++)
#pragma unroll
        for (int j = 0; j < 4; j++) acc[i][j] = 0.f;

#pragma unroll
    for (int kt = 0; kt < 8; kt++) {
        uint32_t a[4];
        {
            int row = wid * 16 + (mat & 1) * 8 + lr;
            int col = kt * 16 + (mat >> 1) * 8;
            ldsm4(su32(As + row * 136 + col), a[0], a[1], a[2], a[3]);
        }
#pragma unroll
        for (int nq = 0; nq < 8; nq++) {
            int nrow = nq * 16 + (mat >> 1) * 8 + lr;
            int col  = kt * 16 + (mat & 1) * 8;
            uint32_t r0, r1, r2, r3;
            ldsm4(su32(Bs + nrow * 136 + col), r0, r1, r2, r3);
            uint32_t bA[2] = {r0, r1}, bB[2] = {r2, r3};
            mma16816(acc[nq * 2], a, bA);
            mma16816(acc[nq * 2 + 1], a, bB);
        }
    }

    float s0 = 0.f, s1 = 0.f;
#pragma unroll
    for (int nt = 0; nt < 16; nt++) {
        int c = nt * 8 + 2 * (lane & 3);
        float2 bb = *(float2*)&abw[c];
        float2 ww = *(float2*)&abw[128 + c];
        s0 += tanh_f(acc[nt][0] + bb.x) * ww.x + tanh_f(acc[nt][1] + bb.y) * ww.y;
        s1 += tanh_f(acc[nt][2] + bb.x) * ww.x + tanh_f(acc[nt][3] + bb.y) * ww.y;
    }
    s0 += __shfl_xor_sync(0xffffffffu, s0, 1);
    s0 += __shfl_xor_sync(0xffffffffu, s0, 2);
    s1 += __shfl_xor_sync(0xffffffffu, s1, 1);
    s1 += __shfl_xor_sync(0xffffffffu, s1, 2);
    if ((lane & 3) == 0) {
        float bv = ab2[0];
        int r = m0 + wid * 16 + (lane >> 2);
        scores[r]     = s0 + bv;
        scores[r + 8] = s1 + bv;
    }
}

// ---------------------------------------------------------------------------
// Softmax over T + context + MLP head. One block per batch row, 128 threads.
// ---------------------------------------------------------------------------
__global__ __launch_bounds__(128)
void head_kernel(const __half* __restrict__ seq,
                 const float* __restrict__ scores,
                 const float* __restrict__ fw1, const float* __restrict__ fb1,
                 const float* __restrict__ fw2, const float* __restrict__ fb2,
                 const float* __restrict__ fw3, const float* __restrict__ fb3,
                 float* __restrict__ out)
{
    extern __shared__ float sm[];
    float* wbuf = sm;                    // [128*129]
    float* attn = wbuf + 128 * 129;      // [256]
    float* ctx  = attn + 256;            // [128]
    float* h1   = ctx + 128;             // [128]
    float* h2   = h1 + 128;              // [64]
    float* red  = h2 + 64;               // [4]

    const int b = blockIdx.x;
    const int tid = threadIdx.x;
    const int wid = tid >> 5;
    const int lid = tid & 31;

    float s0 = scores[(size_t)b * Tc + tid];
    float s1 = scores[(size_t)b * Tc + 128 + tid];
    float mx = fmaxf(s0, s1);
#pragma unroll
    for (int off = 16; off > 0; off >>= 1)
        mx = fmaxf(mx, __shfl_xor_sync(0xffffffffu, mx, off));
    if (lid == 0) red[wid] = mx;
    __syncthreads();
    float m4 = fmaxf(fmaxf(red[0], red[1]), fmaxf(red[2], red[3]));
    __syncthreads();

    float e0 = __expf(s0 - m4);
    float e1 = __expf(s1 - m4);
    float ps = e0 + e1;
#pragma unroll
    for (int off = 16; off > 0; off >>= 1)
        ps += __shfl_xor_sync(0xffffffffu, ps, off);
    if (lid == 0) red[wid] = ps;
    __syncthreads();
    float total = red[0] + red[1] + red[2] + red[3];
    float inv = __fdividef(1.0f, total);
    attn[tid]       = e0 * inv;
    attn[tid + 128] = e1 * inv;
    __syncthreads();

    {
        const __half* sp = seq + (size_t)b * Tc * Hc + tid;
        float acc = 0.f;
#pragma unroll 4
        for (int t = 0; t < Tc; t++)
            acc = fmaf(attn[t], __half2float(sp[(size_t)t * Hc]), acc);
        ctx[tid] = acc;
    }

    for (int idx = tid; idx < 128 * 128; idx += 128) {
        int j = idx >> 7, k = idx & 127;
        wbuf[j * 129 + k] = fw1[idx];
    }
    __syncthreads();
    {
        float a1 = fb1[tid];
        const float* wr = wbuf + tid * 129;
#pragma unroll 4
        for (int k = 0; k < 128; k++) a1 = fmaf(wr[k], ctx[k], a1);
        h1[tid] = fmaxf(a1, 0.f);
    }
    __syncthreads();

    for (int idx = tid; idx < 64 * 128; idx += 128) {
        int j = idx >> 7, k = idx & 127;
        wbuf[j * 129 + k] = fw2[idx];
    }
    __syncthreads();
    if (tid < 64) {
        float a2 = fb2[tid];
        const float* wr = wbuf + tid * 129;
#pragma unroll 4
        for (int k = 0; k < 128; k++) a2 = fmaf(wr[k], h1[k], a2);
        h2[tid] = fmaxf(a2, 0.f);
    }
    __syncthreads();

    float p = (tid < 64) ? fw3[tid] * h2[tid] : 0.f;
#pragma unroll
    for (int off = 16; off > 0; off >>= 1)
        p += __shfl_xor_sync(0xffffffffu, p, off);
    if (lid == 0) red[wid] = p;
    __syncthreads();
    if (tid == 0) out[b] = red[0] + red[1] + red[2] + red[3] + fb3[0];
}

// ---------------------------------------------------------------------------
// Launch
// ---------------------------------------------------------------------------
extern "C" void kernel_launch(void* const* d_in, const int* in_sizes, int n_in,
                              void* d_out, int out_size)
{
    const float* x     = (const float*)d_in[0];
    const float* w_ih0 = (const float*)d_in[1];
    const float* w_hh0 = (const float*)d_in[2];
    const float* b_ih0 = (const float*)d_in[3];
    const float* b_hh0 = (const float*)d_in[4];
    const float* w_ih1 = (const float*)d_in[5];
    const float* w_hh1 = (const float*)d_in[6];
    const float* b_ih1 = (const float*)d_in[7];
    const float* b_hh1 = (const float*)d_in[8];
    const float* aw1   = (const float*)d_in[9];
    const float* ab1   = (const float*)d_in[10];
    const float* aw2   = (const float*)d_in[11];
    const float* ab2   = (const float*)d_in[12];
    const float* fw1   = (const float*)d_in[13];
    const float* fb1   = (const float*)d_in[14];
    const float* fw2   = (const float*)d_in[15];
    const float* fb2   = (const float*)d_in[16];
    const float* fw3   = (const float*)d_in[17];
    const float* fb3   = (const float*)d_in[18];
    float* out = (float*)d_out;

    __half *pre_p, *seq0_p, *seq1_p;
    float *scores_p;
    cudaGetSymbolAddress((void**)&pre_p,    g_pre);
    cudaGetSymbolAddress((void**)&seq0_p,   g_seq0);
    cudaGetSymbolAddress((void**)&seq1_p,   g_seq1);
    cudaGetSymbolAddress((void**)&scores_p, g_scores);

    const int sm_g64  = 2 * 128 * 72 * 2 + 512;    // 37376
    const int sm_g128 = 2 * 128 * 136 * 2 + 512;   // 70144
    const int sm_attn = 2 * 128 * 136 * 2 + 1024;  // 70656
    const int sm_head = (128 * 129 + 256 + 128 + 128 + 64 + 4) * 4;

    cudaFuncSetAttribute(gemm_pre_hmma<64, false>, cudaFuncAttributeMaxDynamicSharedMemorySize, sm_g64);
    cudaFuncSetAttribute(gemm_pre_hmma<128, true>, cudaFuncAttributeMaxDynamicSharedMemorySize, sm_g128);
    cudaFuncSetAttribute(attn_score_hmma,          cudaFuncAttributeMaxDynamicSharedMemorySize, sm_attn);
    cudaFuncSetAttribute(head_kernel,              cudaFuncAttributeMaxDynamicSharedMemorySize, sm_head);

    dim3 ggrid(Mc / 128, 4);

    // Layer 0
    gemm_pre_hmma<64, false><<<ggrid, 256, sm_g64>>>(x, w_ih0, b_ih0, b_hh0, pre_p);
    lstm_rec_hmma<<<Bc / 16, 256>>>(pre_p, w_hh0, seq0_p);

    // Layer 1
    gemm_pre_hmma<128, true><<<ggrid, 256, sm_g128>>>(seq0_p, w_ih1, b_ih1, b_hh1, pre_p);
    lstm_rec_hmma<<<Bc / 16, 256>>>(pre_p, w_hh1, seq1_p);

    // Attention scores
    attn_score_hmma<<<Mc / 128, 256, sm_attn>>>(seq1_p, aw1, ab1, aw2, ab2, scores_p);

    // Softmax + context + MLP head
    head_kernel<<<Bc, 128, sm_head>>>(seq1_p, scores_p, fw1, fb1, fw2, fb2, fw3, fb3, out);
}

// round 3
// speedup vs baseline: 4.3870x; 1.1950x over previous
#include <cuda_runtime.h>
#include <cuda_fp16.h>
#include <cstdint>

#define Bc 2048
#define Tc 256
#define Ic 64
#define Hc 128
#define Gc 512
#define Mc (Bc * Tc)

// ---------------------------------------------------------------------------
// Scratch (device globals; no allocation allowed)
// ---------------------------------------------------------------------------
__device__ __half g_pre[(size_t)Mc * Gc];        // [B][T][4H] fp16 (row m = b*T+t)
__device__ __half g_seq0[(size_t)Mc * Hc];       // layer0 hidden [B][T][H] fp16
__device__ __half g_seq1[(size_t)Mc * Hc];       // layer1 hidden [B][T][H] fp16
__device__ float  g_scores[(size_t)Bc * Tc];     // attention logits [B][T]

// ---------------------------------------------------------------------------
// PTX helpers
// ---------------------------------------------------------------------------
__device__ __forceinline__ uint32_t su32(const void* p) {
    return (uint32_t)__cvta_generic_to_shared(p);
}
__device__ __forceinline__ void ldsm4(uint32_t a, uint32_t& r0, uint32_t& r1,
                                      uint32_t& r2, uint32_t& r3) {
    asm volatile("ldmatrix.sync.aligned.m8n8.x4.shared.b16 {%0,%1,%2,%3},[%4];"
                 : "=r"(r0), "=r"(r1), "=r"(r2), "=r"(r3) : "r"(a));
}
__device__ __forceinline__ void mma16816(float* d, const uint32_t* a, const uint32_t* b) {
    asm volatile(
        "mma.sync.aligned.m16n8k16.row.col.f32.f16.f16.f32 "
        "{%0,%1,%2,%3},{%4,%5,%6,%7},{%8,%9},{%0,%1,%2,%3};"
        : "+f"(d[0]), "+f"(d[1]), "+f"(d[2]), "+f"(d[3])
        : "r"(a[0]), "r"(a[1]), "r"(a[2]), "r"(a[3]), "r"(b[0]), "r"(b[1]));
}
__device__ __forceinline__ float tanh_f(float x) {
    float y; asm("tanh.approx.f32 %0,%1;" : "=f"(y) : "f"(x)); return y;
}
__device__ __forceinline__ float sig_f(float x) {
    return fmaf(tanh_f(0.5f * x), 0.5f, 0.5f);
}
__device__ __forceinline__ void cpa16(uint32_t d, const void* s) {
    asm volatile("cp.async.cg.shared.global [%0],[%1],16;" :: "r"(d), "l"(s));
}

// ---------------------------------------------------------------------------
// Pre-GEMM (HMMA): out[m][n] = A[m]·W[n] + b1[n] + b2[n], fp16 out, m-major
// Block tile 128m x 128n, full K. 8 warps (4m x 2n), warp tile 32m x 64n.
// ---------------------------------------------------------------------------
template <int K, bool AHALF>
__global__ __launch_bounds__(256)
void gemm_pre_hmma(const void* __restrict__ Araw,
                   const float* __restrict__ W,
                   const float* __restrict__ b1f,
                   const float* __restrict__ b2f,
                   __half* __restrict__ out)
{
    constexpr int KP = K + 8;
    extern __shared__ char smraw[];
    __half* As = (__half*)smraw;            // [128][KP]
    __half* Bs = As + 128 * KP;             // [128][KP]  (W rows n0..n0+127)
    float*  bsum = (float*)(Bs + 128 * KP); // [128]

    const int tid = threadIdx.x;
    const int m0 = blockIdx.x * 128, n0 = blockIdx.y * 128;

    if (AHALF) {
        const uint4* Ag = (const uint4*)((const __half*)Araw + (size_t)m0 * K);
        for (int i = tid; i < 128 * K / 8; i += 256) {
            int r = i / (K / 8), ch = i % (K / 8);
            *(uint4*)(As + r * KP + ch * 8) = Ag[i];
        }
    } else {
        const float4* Ag = (const float4*)((const float*)Araw + (size_t)m0 * K);
        for (int i = tid; i < 128 * K / 4; i += 256) {
            int r = i / (K / 4), ch = i % (K / 4);
            float4 v = Ag[i];
            *(__half2*)(As + r * KP + ch * 4)     = __floats2half2_rn(v.x, v.y);
            *(__half2*)(As + r * KP + ch * 4 + 2) = __floats2half2_rn(v.z, v.w);
        }
    }
    {
        const float4* Wg = (const float4*)(W + (size_t)n0 * K);
        for (int i = tid; i < 128 * K / 4; i += 256) {
            int r = i / (K / 4), ch = i % (K / 4);
            float4 v = Wg[i];
            *(__half2*)(Bs + r * KP + ch * 4)     = __floats2half2_rn(v.x, v.y);
            *(__half2*)(Bs + r * KP + ch * 4 + 2) = __floats2half2_rn(v.z, v.w);
        }
    }
    if (tid < 128) bsum[tid] = b1f[n0 + tid] + b2f[n0 + tid];
    __syncthreads();

    const int wid = tid >> 5, lane = tid & 31;
    const int wm = wid & 3, wn = wid >> 2;
    const int mat = lane >> 3, lr = lane & 7;

    float acc[2][8][4];
#pragma unroll
    for (int i = 0; i < 2; i++)
#pragma unroll
        for (int j = 0; j < 8; j++)
#pragma unroll
            for (int l = 0; l < 4; l++) acc[i][j][l] = 0.f;

#pragma unroll
    for (int kt = 0; kt < K / 16; kt++) {
        uint32_t a[2][4];
#pragma unroll
        for (int mt = 0; mt < 2; mt++) {
            int row = wm * 32 + mt * 16 + (mat & 1) * 8 + lr;
            int col = kt * 16 + (mat >> 1) * 8;
            ldsm4(su32(As + row * KP + col), a[mt][0], a[mt][1], a[mt][2], a[mt][3]);
        }
        uint32_t b[8][2];
#pragma unroll
        for (int nq = 0; nq < 4; nq++) {
            int nrow = wn * 64 + nq * 16 + (mat >> 1) * 8 + lr;
            int col  = kt * 16 + (mat & 1) * 8;
            uint32_t r0, r1, r2, r3;
            ldsm4(su32(Bs + nrow * KP + col), r0, r1, r2, r3);
            b[nq * 2][0] = r0; b[nq * 2][1] = r1;
            b[nq * 2 + 1][0] = r2; b[nq * 2 + 1][1] = r3;
        }
#pragma unroll
        for (int mt = 0; mt < 2; mt++)
#pragma unroll
            for (int nt = 0; nt < 8; nt++)
                mma16816(acc[mt][nt], a[mt], b[nt]);
    }

    // epilogue: add bias, store fp16 at [m][n] (coalesced rows)
#pragma unroll
    for (int mt = 0; mt < 2; mt++) {
#pragma unroll
        for (int nt = 0; nt < 8; nt++) {
            int lc = wn * 64 + nt * 8 + 2 * (lane & 3);
            float2 bs = *(float2*)&bsum[lc];
            int c = n0 + lc;
#pragma unroll
            for (int hh = 0; hh < 2; hh++) {
                int r = m0 + wm * 32 + mt * 16 + (lane >> 2) + hh * 8;
                size_t off = (size_t)r * Gc + c;
                *(__half2*)&out[off] =
                    __floats2half2_rn(acc[mt][nt][hh * 2] + bs.x,
                                      acc[mt][nt][hh * 2 + 1] + bs.y);
            }
        }
    }
}

// ---------------------------------------------------------------------------
// LSTM recurrence (HMMA): block = 16 batch rows, 16 warps (512 threads).
// Warp w owns h-column group 8*w across all 4 gates (register-local cell).
// w_hh in registers as fp16 B-fragments (64 regs/thread).
// pre [B][T][G]; staged by cp.async double-buffer.
// ---------------------------------------------------------------------------
__global__ __launch_bounds__(512, 1)
void lstm_rec_hmma(const __half* __restrict__ pre,    // [B][T][512]
                   const float*  __restrict__ w_hh,   // [512][128]
                   __half* __restrict__ seqout)       // [B][T][128]
{
    __shared__ __half h_sm[2][16][136];
    __shared__ __half pre_sm[2][16][520];

    const int tid = threadIdx.x, wid = tid >> 5, lane = tid & 31;
    const int b0 = blockIdx.x * 16;
    const int r_lo = lane >> 2;
    const int c_loc = 2 * (lane & 3);

    // Persistent B fragments: warp w owns gate cols n = 128*g + 8*w (+ lane n_off)
    uint32_t bf[8][4][2];
    {
#pragma unroll
        for (int g = 0; g < 4; g++) {
            int n = 128 * g + 8 * wid + r_lo;
            const float* wr = w_hh + (size_t)n * Hc + c_loc;
#pragma unroll
            for (int kt = 0; kt < 8; kt++) {
                float2 v0 = *(const float2*)(wr + kt * 16);
                float2 v1 = *(const float2*)(wr + kt * 16 + 8);
                __half2 h0 = __floats2half2_rn(v0.x, v0.y);
                __half2 h1 = __floats2half2_rn(v1.x, v1.y);
                bf[kt][g][0] = *(uint32_t*)&h0;
                bf[kt][g][1] = *(uint32_t*)&h1;
            }
        }
    }

    for (int i = tid; i < 2 * 16 * 136; i += 512)
        ((__half*)h_sm)[i] = __float2half(0.f);

    // prefetch pre(t=0): 16 rows x 1KB
#pragma unroll
    for (int j = 0; j < 2; j++) {
        int idx = tid + j * 512;
        int r = idx >> 6, ch = idx & 63;
        cpa16(su32(&pre_sm[0][r][ch * 8]),
              pre + ((size_t)(b0 + r) * Tc + 0) * Gc + ch * 8);
    }
    asm volatile("cp.async.commit_group;");

    float cst[4];
#pragma unroll
    for (int j = 0; j < 4; j++) cst[j] = 0.f;

    asm volatile("cp.async.wait_group 0;");
    __syncthreads();

    for (int t = 0; t < Tc; t++) {
        const int cur = t & 1, nxt = cur ^ 1;

        // acc init from pre tile (direct conflict-free half2 loads)
        float acc[4][4];
#pragma unroll
        for (int g = 0; g < 4; g++) {
            int cc = 128 * g + 8 * wid + c_loc;
            float2 lo = __half22float2(*(const __half2*)&pre_sm[cur][r_lo][cc]);
            float2 hi = __half22float2(*(const __half2*)&pre_sm[cur][r_lo + 8][cc]);
            acc[g][0] = lo.x; acc[g][1] = lo.y;
            acc[g][2] = hi.x; acc[g][3] = hi.y;
        }

        // prefetch pre(t+1) (hidden behind MMA)
        if (t + 1 < Tc) {
#pragma unroll
            for (int j = 0; j < 2; j++) {
                int idx = tid + j * 512;
                int r = idx >> 6, ch = idx & 63;
                cpa16(su32(&pre_sm[nxt][r][ch * 8]),
                      pre + ((size_t)(b0 + r) * Tc + (t + 1)) * Gc + ch * 8);
            }
        }
        asm volatile("cp.async.commit_group;");

        // gates += h(t-1) @ w_hh^T
#pragma unroll
        for (int kt = 0; kt < 8; kt++) {
            uint32_t a[4];
            a[0] = *(const uint32_t*)&h_sm[cur][r_lo    ][kt * 16 + c_loc];
            a[1] = *(const uint32_t*)&h_sm[cur][r_lo + 8][kt * 16 + c_loc];
            a[2] = *(const uint32_t*)&h_sm[cur][r_lo    ][kt * 16 + c_loc + 8];
            a[3] = *(const uint32_t*)&h_sm[cur][r_lo + 8][kt * 16 + c_loc + 8];
#pragma unroll
            for (int g = 0; g < 4; g++) mma16816(acc[g], a, bf[kt][g]);
        }

        // register-local LSTM cell: thread owns 4 elements (2 rows x 2 cols)
#pragma unroll
        for (int jr = 0; jr < 2; jr++) {
            float hv0, hv1;
#pragma unroll
            for (int jc = 0; jc < 2; jc++) {
                int j = jr * 2 + jc;
                float i_ = sig_f(acc[0][j]);
                float f_ = sig_f(acc[1][j]);
                float z_ = tanh_f(acc[2][j]);
                float o_ = sig_f(acc[3][j]);
                float cn = fmaf(f_, cst[j], i_ * z_);
                cst[j] = cn;
                float hv = o_ * tanh_f(cn);
                if (jc == 0) hv0 = hv; else hv1 = hv;
            }
            __half2 hh = __floats2half2_rn(hv0, hv1);
            int rr = r_lo + jr * 8;
            int cc = 8 * wid + c_loc;
            *(__half2*)&h_sm[nxt][rr][cc] = hh;
            *(__half2*)&seqout[((size_t)(b0 + rr) * Tc + t) * Hc + cc] = hh;
        }
        asm volatile("cp.async.wait_group 0;");
        __syncthreads();
    }
}

// ---------------------------------------------------------------------------
// Attention scores (HMMA): s[m] = tanh(seq[m]@aw1^T + ab1)·aw2 + ab2
// ---------------------------------------------------------------------------
__global__ __launch_bounds__(256)
void attn_score_hmma(const __half* __restrict__ seq,
                     const float* __restrict__ aw1,
                     const float* __restrict__ ab1,
                     const float* __restrict__ aw2,
                     const float* __restrict__ ab2,
                     float* __restrict__ scores)
{
    extern __shared__ char smraw[];
    __half* As = (__half*)smraw;             // [128][136]
    __half* Bs = As + 128 * 136;             // [128][136] aw1 as [n][k]
    float*  abw = (float*)(Bs + 128 * 136);  // [256] = ab1 | aw2

    const int tid = threadIdx.x, wid = tid >> 5, lane = tid & 31;
    const int m0 = blockIdx.x * 128;

    {
        const uint4* Ag = (const uint4*)(seq + (size_t)m0 * Hc);
        for (int i = tid; i < 128 * 16; i += 256) {
            int r = i >> 4, ch = i & 15;
            *(uint4*)(As + r * 136 + ch * 8) = Ag[i];
        }
        const float4* Wg = (const float4*)aw1;
        for (int i = tid; i < 128 * 32; i += 256) {
            int r = i >> 5, ch = i & 31;
            float4 v = Wg[i];
            *(__half2*)(Bs + r * 136 + ch * 4)     = __floats2half2_rn(v.x, v.y);
            *(__half2*)(Bs + r * 136 + ch * 4 + 2) = __floats2half2_rn(v.z, v.w);
        }
        if (tid < 128) abw[tid] = ab1[tid];
        else if (tid < 256) abw[tid] = aw2[tid - 128];
    }
    __syncthreads();

    const int mat = lane >> 3, lr = lane & 7;
    float acc[16][4];
#pragma unroll
    for (int i = 0; i < 16; i++)
#pragma unroll
        for (int j = 0; j < 4; j++) acc[i][j] = 0.f;

#pragma unroll
    for (int kt = 0; kt < 8; kt++) {
        uint32_t a[4];
        {
            int row = wid * 16 + (mat & 1) * 8 + lr;
            int col = kt * 16 + (mat >> 1) * 8;
            ldsm4(su32(As + row * 136 + col), a[0], a[1], a[2], a[3]);
        }
#pragma unroll
        for (int nq = 0; nq < 8; nq++) {
            int nrow = nq * 16 + (mat >> 1) * 8 + lr;
            int col  = kt * 16 + (mat & 1) * 8;
            uint32_t r0, r1, r2, r3;
            ldsm4(su32(Bs + nrow * 136 + col), r0, r1, r2, r3);
            uint32_t bA[2] = {r0, r1}, bB[2] = {r2, r3};
            mma16816(acc[nq * 2], a, bA);
            mma16816(acc[nq * 2 + 1], a, bB);
        }
    }

    float s0 = 0.f, s1 = 0.f;
#pragma unroll
    for (int nt = 0; nt < 16; nt++) {
        int c = nt * 8 + 2 * (lane & 3);
        float2 bb = *(float2*)&abw[c];
        float2 ww = *(float2*)&abw[128 + c];
        s0 += tanh_f(acc[nt][0] + bb.x) * ww.x + tanh_f(acc[nt][1] + bb.y) * ww.y;
        s1 += tanh_f(acc[nt][2] + bb.x) * ww.x + tanh_f(acc[nt][3] + bb.y) * ww.y;
    }
    s0 += __shfl_xor_sync(0xffffffffu, s0, 1);
    s0 += __shfl_xor_sync(0xffffffffu, s0, 2);
    s1 += __shfl_xor_sync(0xffffffffu, s1, 1);
    s1 += __shfl_xor_sync(0xffffffffu, s1, 2);
    if ((lane & 3) == 0) {
        float bv = ab2[0];
        int r = m0 + wid * 16 + (lane >> 2);
        scores[r]     = s0 + bv;
        scores[r + 8] = s1 + bv;
    }
}

// ---------------------------------------------------------------------------
// Softmax over T + context + MLP head. One block per batch row, 128 threads.
// ---------------------------------------------------------------------------
__global__ __launch_bounds__(128)
void head_kernel(const __half* __restrict__ seq,
                 const float* __restrict__ scores,
                 const float* __restrict__ fw1, const float* __restrict__ fb1,
                 const float* __restrict__ fw2, const float* __restrict__ fb2,
                 const float* __restrict__ fw3, const float* __restrict__ fb3,
                 float* __restrict__ out)
{
    extern __shared__ float sm[];
    float* wbuf = sm;                    // [128*129]
    float* attn = wbuf + 128 * 129;      // [256]
    float* ctx  = attn + 256;            // [128]
    float* h1   = ctx + 128;             // [128]
    float* h2   = h1 + 128;              // [64]
    float* red  = h2 + 64;               // [4]

    const int b = blockIdx.x;
    const int tid = threadIdx.x;
    const int wid = tid >> 5;
    const int lid = tid & 31;

    float s0 = scores[(size_t)b * Tc + tid];
    float s1 = scores[(size_t)b * Tc + 128 + tid];
    float mx = fmaxf(s0, s1);
#pragma unroll
    for (int off = 16; off > 0; off >>= 1)
        mx = fmaxf(mx, __shfl_xor_sync(0xffffffffu, mx, off));
    if (lid == 0) red[wid] = mx;
    __syncthreads();
    float m4 = fmaxf(fmaxf(red[0], red[1]), fmaxf(red[2], red[3]));
    __syncthreads();

    float e0 = __expf(s0 - m4);
    float e1 = __expf(s1 - m4);
    float ps = e0 + e1;
#pragma unroll
    for (int off = 16; off > 0; off >>= 1)
        ps += __shfl_xor_sync(0xffffffffu, ps, off);
    if (lid == 0) red[wid] = ps;
    __syncthreads();
    float total = red[0] + red[1] + red[2] + red[3];
    float inv = __fdividef(1.0f, total);
    attn[tid]       = e0 * inv;
    attn[tid + 128] = e1 * inv;
    __syncthreads();

    {
        const __half* sp = seq + (size_t)b * Tc * Hc + tid;
        float acc = 0.f;
#pragma unroll 4
        for (int t = 0; t < Tc; t++)
            acc = fmaf(attn[t], __half2float(sp[(size_t)t * Hc]), acc);
        ctx[tid] = acc;
    }

    for (int idx = tid; idx < 128 * 128; idx += 128) {
        int j = idx >> 7, k = idx & 127;
        wbuf[j * 129 + k] = fw1[idx];
    }
    __syncthreads();
    {
        float a1 = fb1[tid];
        const float* wr = wbuf + tid * 129;
#pragma unroll 4
        for (int k = 0; k < 128; k++) a1 = fmaf(wr[k], ctx[k], a1);
        h1[tid] = fmaxf(a1, 0.f);
    }
    __syncthreads();

    for (int idx = tid; idx < 64 * 128; idx += 128) {
        int j = idx >> 7, k = idx & 127;
        wbuf[j * 129 + k] = fw2[idx];
    }
    __syncthreads();
    if (tid < 64) {
        float a2 = fb2[tid];
        const float* wr = wbuf + tid * 129;
#pragma unroll 4
        for (int k = 0; k < 128; k++) a2 = fmaf(wr[k], h1[k], a2);
        h2[tid] = fmaxf(a2, 0.f);
    }
    __syncthreads();

    float p = (tid < 64) ? fw3[tid] * h2[tid] : 0.f;
#pragma unroll
    for (int off = 16; off > 0; off >>= 1)
        p += __shfl_xor_sync(0xffffffffu, p, off);
    if (lid == 0) red[wid] = p;
    __syncthreads();
    if (tid == 0) out[b] = red[0] + red[1] + red[2] + red[3] + fb3[0];
}

// ---------------------------------------------------------------------------
// Launch
// ---------------------------------------------------------------------------
extern "C" void kernel_launch(void* const* d_in, const int* in_sizes, int n_in,
                              void* d_out, int out_size)
{
    const float* x     = (const float*)d_in[0];
    const float* w_ih0 = (const float*)d_in[1];
    const float* w_hh0 = (const float*)d_in[2];
    const float* b_ih0 = (const float*)d_in[3];
    const float* b_hh0 = (const float*)d_in[4];
    const float* w_ih1 = (const float*)d_in[5];
    const float* w_hh1 = (const float*)d_in[6];
    const float* b_ih1 = (const float*)d_in[7];
    const float* b_hh1 = (const float*)d_in[8];
    const float* aw1   = (const float*)d_in[9];
    const float* ab1   = (const float*)d_in[10];
    const float* aw2   = (const float*)d_in[11];
    const float* ab2   = (const float*)d_in[12];
    const float* fw1   = (const float*)d_in[13];
    const float* fb1   = (const float*)d_in[14];
    const float* fw2   = (const float*)d_in[15];
    const float* fb2   = (const float*)d_in[16];
    const float* fw3   = (const float*)d_in[17];
    const float* fb3   = (const float*)d_in[18];
    float* out = (float*)d_out;

    __half *pre_p, *seq0_p, *seq1_p;
    float *scores_p;
    cudaGetSymbolAddress((void**)&pre_p,    g_pre);
    cudaGetSymbolAddress((void**)&seq0_p,   g_seq0);
    cudaGetSymbolAddress((void**)&seq1_p,   g_seq1);
    cudaGetSymbolAddress((void**)&scores_p, g_scores);

    const int sm_g64  = 2 * 128 * 72 * 2 + 512;    // 37376
    const int sm_g128 = 2 * 128 * 136 * 2 + 512;   // 70144
    const int sm_attn = 2 * 128 * 136 * 2 + 1024;  // 70656
    const int sm_head = (128 * 129 + 256 + 128 + 128 + 64 + 4) * 4;

    cudaFuncSetAttribute(gemm_pre_hmma<64, false>, cudaFuncAttributeMaxDynamicSharedMemorySize, sm_g64);
    cudaFuncSetAttribute(gemm_pre_hmma<128, true>, cudaFuncAttributeMaxDynamicSharedMemorySize, sm_g128);
    cudaFuncSetAttribute(attn_score_hmma,          cudaFuncAttributeMaxDynamicSharedMemorySize, sm_attn);
    cudaFuncSetAttribute(head_kernel,              cudaFuncAttributeMaxDynamicSharedMemorySize, sm_head);

    dim3 ggrid(Mc / 128, 4);

    // Layer 0
    gemm_pre_hmma<64, false><<<ggrid, 256, sm_g64>>>(x, w_ih0, b_ih0, b_hh0, pre_p);
    lstm_rec_hmma<<<Bc / 16, 512>>>(pre_p, w_hh0, seq0_p);

    // Layer 1
    gemm_pre_hmma<128, true><<<ggrid, 256, sm_g128>>>(seq0_p, w_ih1, b_ih1, b_hh1, pre_p);
    lstm_rec_hmma<<<Bc / 16, 512>>>(pre_p, w_hh1, seq1_p);

    // Attention scores
    attn_score_hmma<<<Mc / 128, 256, sm_attn>>>(seq1_p, aw1, ab1, aw2, ab2, scores_p);

    // Softmax + context + MLP head
    head_kernel<<<Bc, 128, sm_head>>>(seq1_p, scores_p, fw1, fb1, fw2, fb2, fw3, fb3, out);
}